// round 1
// baseline (speedup 1.0000x reference)
#include <cuda_runtime.h>
#include <math.h>

// ---------------- problem constants ----------------
#define D_MODEL 1024
#define DFF_DIM 4096
#define NTOK    2048          // B*S = 2*1024
#define NHEAD   16
#define DH      64
#define NLAYER  3

// ---------------- scratch (no allocs allowed) ----------------
__device__ float g_cur[NTOK * D_MODEL];
__device__ float g_q  [NTOK * D_MODEL];
__device__ float g_k  [NTOK * D_MODEL];
__device__ float g_v  [NTOK * D_MODEL];
__device__ float g_qf [NTOK * D_MODEL];
__device__ float g_kf [NTOK * D_MODEL];
__device__ float g_h  [NTOK * D_MODEL];
__device__ float g_ffn[NTOK * DFF_DIM];

// ---------------- copy ----------------
__global__ void copy_kernel(const float* __restrict__ src, float* __restrict__ dst, int n)
{
    int i = blockIdx.x * blockDim.x + threadIdx.x;
    if (i < n) dst[i] = src[i];
}

// ---------------- SGEMM: C = A[MxK] * B[KxN] + bias, optional relu ----------------
// 128x128 tile, BK=16, 256 threads, 8x8 per thread.
__global__ __launch_bounds__(256) void sgemm_kernel(
    const float* __restrict__ A, const float* __restrict__ B,
    const float* __restrict__ bias, float* __restrict__ C,
    int M, int N, int K, int do_relu)
{
    __shared__ __align__(16) float As[16][132];
    __shared__ __align__(16) float Bs[16][132];

    const int tid = threadIdx.x;
    const int bm  = blockIdx.y * 128;
    const int bn  = blockIdx.x * 128;
    const int tr  = (tid >> 4) * 8;   // 0..120
    const int tc  = (tid & 15) * 8;   // 0..120

    const int arow = tid >> 2;        // 0..63
    const int acol = (tid & 3) * 4;   // 0,4,8,12
    const int brow = tid >> 5;        // 0..7
    const int bcol = (tid & 31) * 4;  // 0..124

    const float* Aptr = A + (size_t)(bm + arow) * K + acol;
    const float* Bptr = B + (size_t)brow * N + bn + bcol;

    float acc[8][8];
    #pragma unroll
    for (int i = 0; i < 8; i++)
        #pragma unroll
        for (int j = 0; j < 8; j++) acc[i][j] = 0.f;

    for (int k0 = 0; k0 < K; k0 += 16) {
        float4 a0 = *(const float4*)(Aptr + k0);
        float4 a1 = *(const float4*)(Aptr + (size_t)64 * K + k0);
        float4 b0 = *(const float4*)(Bptr + (size_t)k0 * N);
        float4 b1 = *(const float4*)(Bptr + (size_t)(k0 + 8) * N);

        __syncthreads();
        As[acol + 0][arow]      = a0.x; As[acol + 1][arow]      = a0.y;
        As[acol + 2][arow]      = a0.z; As[acol + 3][arow]      = a0.w;
        As[acol + 0][arow + 64] = a1.x; As[acol + 1][arow + 64] = a1.y;
        As[acol + 2][arow + 64] = a1.z; As[acol + 3][arow + 64] = a1.w;
        *(float4*)&Bs[brow][bcol]     = b0;
        *(float4*)&Bs[brow + 8][bcol] = b1;
        __syncthreads();

        #pragma unroll
        for (int kk = 0; kk < 16; kk++) {
            float ra[8], rb[8];
            *(float4*)(ra)     = *(const float4*)&As[kk][tr];
            *(float4*)(ra + 4) = *(const float4*)&As[kk][tr + 4];
            *(float4*)(rb)     = *(const float4*)&Bs[kk][tc];
            *(float4*)(rb + 4) = *(const float4*)&Bs[kk][tc + 4];
            #pragma unroll
            for (int i = 0; i < 8; i++)
                #pragma unroll
                for (int j = 0; j < 8; j++)
                    acc[i][j] = fmaf(ra[i], rb[j], acc[i][j]);
        }
    }

    #pragma unroll
    for (int i = 0; i < 8; i++) {
        size_t row = (size_t)(bm + tr + i);
        #pragma unroll
        for (int j = 0; j < 8; j += 4) {
            int col = bn + tc + j;
            float4 o;
            o.x = acc[i][j + 0] + bias[col + 0];
            o.y = acc[i][j + 1] + bias[col + 1];
            o.z = acc[i][j + 2] + bias[col + 2];
            o.w = acc[i][j + 3] + bias[col + 3];
            if (do_relu) {
                o.x = fmaxf(o.x, 0.f); o.y = fmaxf(o.y, 0.f);
                o.z = fmaxf(o.z, 0.f); o.w = fmaxf(o.w, 0.f);
            }
            *(float4*)&C[row * N + col] = o;
        }
    }
}

// ---------------- FAVOR feature map ----------------
// X: [NTOK, D_MODEL] head-block layout. omega: [64,32]. Phi: same layout as X.
// phi[j<32]  = exp(u_j - h) / 8 ;  phi[32+j] = exp(-u_j - h) / 8
__global__ __launch_bounds__(256) void favor_kernel(
    const float* __restrict__ X, const float* __restrict__ omega,
    float* __restrict__ Phi)
{
    __shared__ float om[DH * 32];          // 2048 floats
    __shared__ float xsb[8][DH];

    const int tid = threadIdx.x;
    for (int i = tid; i < DH * 32; i += 256) om[i] = omega[i];

    const int w    = tid >> 5;
    const int lane = tid & 31;
    const int gw   = blockIdx.x * 8 + w;   // 0..32767
    const int token = gw >> 4;
    const int head  = gw & 15;

    const float scale = 0.35355339059327373f;   // 64^-0.25
    const size_t base = (size_t)token * D_MODEL + head * DH;

    float x0 = X[base + lane]      * scale;
    float x1 = X[base + 32 + lane] * scale;
    xsb[w][lane]      = x0;
    xsb[w][lane + 32] = x1;

    float hh = x0 * x0 + x1 * x1;
    #pragma unroll
    for (int o = 16; o; o >>= 1) hh += __shfl_xor_sync(0xffffffffu, hh, o);
    hh *= 0.5f;

    __syncthreads();

    float u = 0.f;
    #pragma unroll
    for (int d = 0; d < DH; d++)
        u = fmaf(xsb[w][d], om[d * 32 + lane], u);

    const float c = 0.125f;   // 64^-0.5
    Phi[base + lane]      = expf(u  - hh) * c;
    Phi[base + 32 + lane] = expf(-u - hh) * c;
}

// ---------------- causal linear attention scan ----------------
// One block per (b,h); thread d owns state column S[:,d] (64 regs).
__global__ __launch_bounds__(64) void scan_kernel(
    const float* __restrict__ Qf, const float* __restrict__ Kf,
    const float* __restrict__ V, float* __restrict__ Out)
{
    const int bh = blockIdx.x;        // 0..31
    const int d  = threadIdx.x;       // 0..63
    __shared__ __align__(16) float qs[64], ks[64], vs[64], zs[64];

    float S[64];
    #pragma unroll
    for (int m = 0; m < 64; m++) S[m] = 0.f;
    zs[d] = 0.f;

    const int b = bh >> 4, hh = bh & 15;
    const size_t base = (size_t)b * 1024 * D_MODEL + hh * DH + d;

    for (int t = 0; t < 1024; t++) {
        const size_t off = base + (size_t)t * D_MODEL;
        __syncthreads();                   // protect prev-iter reads
        qs[d] = Qf[off]; ks[d] = Kf[off]; vs[d] = V[off];
        __syncthreads();
        zs[d] += ks[d];
        __syncthreads();

        const float vd = vs[d];
        float num = 0.f, den = 0.f;
        #pragma unroll
        for (int m4 = 0; m4 < 16; m4++) {
            float4 k4 = *(const float4*)&ks[m4 * 4];
            float4 q4 = *(const float4*)&qs[m4 * 4];
            float4 z4 = *(const float4*)&zs[m4 * 4];
            S[m4*4+0] = fmaf(k4.x, vd, S[m4*4+0]); num = fmaf(q4.x, S[m4*4+0], num); den = fmaf(q4.x, z4.x, den);
            S[m4*4+1] = fmaf(k4.y, vd, S[m4*4+1]); num = fmaf(q4.y, S[m4*4+1], num); den = fmaf(q4.y, z4.y, den);
            S[m4*4+2] = fmaf(k4.z, vd, S[m4*4+2]); num = fmaf(q4.z, S[m4*4+2], num); den = fmaf(q4.z, z4.z, den);
            S[m4*4+3] = fmaf(k4.w, vd, S[m4*4+3]); num = fmaf(q4.w, S[m4*4+3], num); den = fmaf(q4.w, z4.w, den);
        }
        Out[off] = num / (den + 1e-6f);
    }
}

// ---------------- LayerNorm(out = LN(a + r) * g + b) ----------------
__global__ __launch_bounds__(256) void ln_kernel(
    float* __restrict__ out, const float* __restrict__ a,
    const float* __restrict__ r, const float* __restrict__ gam,
    const float* __restrict__ bet)
{
    const int row = blockIdx.x;
    const int tid = threadIdx.x;
    const float* pa = a + (size_t)row * D_MODEL;
    const float* pr = r + (size_t)row * D_MODEL;

    float v[4];
    float s = 0.f, ss = 0.f;
    #pragma unroll
    for (int i = 0; i < 4; i++) {
        int idx = tid + i * 256;
        float t = pa[idx] + pr[idx];
        v[i] = t; s += t; ss = fmaf(t, t, ss);
    }

    __shared__ float red[18];
    #pragma unroll
    for (int o = 16; o; o >>= 1) {
        s  += __shfl_xor_sync(0xffffffffu, s,  o);
        ss += __shfl_xor_sync(0xffffffffu, ss, o);
    }
    const int w = tid >> 5, lane = tid & 31;
    __shared__ float rw[16];
    if (lane == 0) { rw[w] = s; rw[w + 8] = ss; }
    __syncthreads();
    if (tid == 0) {
        float S0 = 0.f, S1 = 0.f;
        #pragma unroll
        for (int i = 0; i < 8; i++) { S0 += rw[i]; S1 += rw[i + 8]; }
        red[16] = S0; red[17] = S1;
    }
    __syncthreads();

    const float mean = red[16] * (1.f / 1024.f);
    const float var  = red[17] * (1.f / 1024.f) - mean * mean;
    const float inv  = rsqrtf(var + 1e-5f);

    float* po = out + (size_t)row * D_MODEL;
    #pragma unroll
    for (int i = 0; i < 4; i++) {
        int idx = tid + i * 256;
        po[idx] = (v[i] - mean) * inv * gam[idx] + bet[idx];
    }
}

// ---------------- launch ----------------
extern "C" void kernel_launch(void* const* d_in, const int* in_sizes, int n_in,
                              void* d_out, int out_size)
{
    const float* x    = (const float*)d_in[0];
    const float* Wq   = (const float*)d_in[1];
    const float* bq   = (const float*)d_in[2];
    const float* Wk   = (const float*)d_in[3];
    const float* bk   = (const float*)d_in[4];
    const float* Wv   = (const float*)d_in[5];
    const float* bv   = (const float*)d_in[6];
    const float* Wo   = (const float*)d_in[7];
    const float* bo   = (const float*)d_in[8];
    const float* omg  = (const float*)d_in[9];
    const float* ln1g = (const float*)d_in[10];
    const float* ln1b = (const float*)d_in[11];
    const float* ln2g = (const float*)d_in[12];
    const float* ln2b = (const float*)d_in[13];
    const float* W1   = (const float*)d_in[14];
    const float* bf1  = (const float*)d_in[15];
    const float* W2   = (const float*)d_in[16];
    const float* bf2  = (const float*)d_in[17];
    float* out = (float*)d_out;

    float *cur, *q, *k, *v, *qf, *kf, *h, *ffn;
    cudaGetSymbolAddress((void**)&cur, g_cur);
    cudaGetSymbolAddress((void**)&q,   g_q);
    cudaGetSymbolAddress((void**)&k,   g_k);
    cudaGetSymbolAddress((void**)&v,   g_v);
    cudaGetSymbolAddress((void**)&qf,  g_qf);
    cudaGetSymbolAddress((void**)&kf,  g_kf);
    cudaGetSymbolAddress((void**)&h,   g_h);
    cudaGetSymbolAddress((void**)&ffn, g_ffn);

    const int nElem = NTOK * D_MODEL;
    copy_kernel<<<(nElem + 255) / 256, 256>>>(x, cur, nElem);

    const dim3 gD(D_MODEL / 128, NTOK / 128);      // (8,16)
    const dim3 gF(DFF_DIM / 128, NTOK / 128);      // (32,16)

    for (int l = 0; l < NLAYER; l++) {
        const size_t wDD  = (size_t)l * D_MODEL * D_MODEL;
        const size_t wDF  = (size_t)l * D_MODEL * DFF_DIM;
        const size_t bD   = (size_t)l * D_MODEL;
        const size_t bF   = (size_t)l * DFF_DIM;
        const size_t oOff = (size_t)l * DH * 32;

        sgemm_kernel<<<gD, 256>>>(cur, Wq + wDD, bq + bD, q, NTOK, D_MODEL, D_MODEL, 0);
        sgemm_kernel<<<gD, 256>>>(cur, Wk + wDD, bk + bD, k, NTOK, D_MODEL, D_MODEL, 0);
        sgemm_kernel<<<gD, 256>>>(cur, Wv + wDD, bv + bD, v, NTOK, D_MODEL, D_MODEL, 0);

        favor_kernel<<<NTOK * NHEAD / 8, 256>>>(q, omg + oOff, qf);
        favor_kernel<<<NTOK * NHEAD / 8, 256>>>(k, omg + oOff, kf);

        scan_kernel<<<32, 64>>>(qf, kf, v, q);     // attn -> q

        sgemm_kernel<<<gD, 256>>>(q, Wo + wDD, bo + bD, k, NTOK, D_MODEL, D_MODEL, 0);  // a -> k
        ln_kernel<<<NTOK, 256>>>(h, cur, k, ln1g + bD, ln1b + bD);                       // h = LN(cur + a)

        sgemm_kernel<<<gF, 256>>>(h, W1 + wDF, bf1 + bF, ffn, NTOK, DFF_DIM, D_MODEL, 1);
        sgemm_kernel<<<gD, 256>>>(ffn, W2 + wDF, bf2 + bD, v, NTOK, D_MODEL, DFF_DIM, 0); // y -> v

        float* dst = (l == NLAYER - 1) ? out : cur;
        ln_kernel<<<NTOK, 256>>>(dst, h, v, ln2g + bD, ln2b + bD);
    }
}

// round 4
// speedup vs baseline: 2.3804x; 2.3804x over previous
#include <cuda_runtime.h>
#include <cstdint>
#include <math.h>

// ---------------- problem constants ----------------
#define D_MODEL 1024
#define DFF_DIM 4096
#define NTOK    2048          // B*S = 2*1024
#define NHEAD   16
#define DH      64
#define NLAYER  3
#define NCHUNK  16            // chunks per sequence
#define CLEN    64            // tokens per chunk

// ---------------- scratch (no allocs allowed) ----------------
__device__ float g_cur[NTOK * D_MODEL];
__device__ float g_q  [NTOK * D_MODEL];
__device__ float g_k  [NTOK * D_MODEL];
__device__ float g_v  [NTOK * D_MODEL];
__device__ float g_qf [NTOK * D_MODEL];
__device__ float g_kf [NTOK * D_MODEL];
__device__ float g_h  [NTOK * D_MODEL];
__device__ float g_ffn[NTOK * DFF_DIM];
__device__ float g_S  [32 * NCHUNK * DH * DH];   // per (b,h,chunk): 64x64 state
__device__ float g_Z  [32 * NCHUNK * DH];        // per (b,h,chunk): 64 z-vector

// ================= helpers =================
__device__ __forceinline__ uint32_t f2tf32(float f) {
    uint32_t u;
    asm("cvt.rna.tf32.f32 %0, %1;" : "=r"(u) : "f"(f));
    return u;
}
__device__ __forceinline__ void mma_tf32(float c[4], uint32_t a0, uint32_t a1,
                                         uint32_t a2, uint32_t a3,
                                         uint32_t b0, uint32_t b1) {
    asm volatile(
        "mma.sync.aligned.m16n8k8.row.col.f32.tf32.tf32.f32 "
        "{%0,%1,%2,%3}, {%4,%5,%6,%7}, {%8,%9}, {%0,%1,%2,%3};"
        : "+f"(c[0]), "+f"(c[1]), "+f"(c[2]), "+f"(c[3])
        : "r"(a0), "r"(a1), "r"(a2), "r"(a3), "r"(b0), "r"(b1));
}

// ================= TF32 tensor-core GEMM =================
// C[M,N] = A[M,K] @ B[K,N] + bias (optional relu).
// 128x128 CTA tile, BK=32, 256 threads (8 warps, warp grid 2m x 4n, warp tile 64x32).
// As: [128][36] (pad 36 -> frag LDS conflict-free), Bs: [32][132].
#define ASTRIDE 36
#define BSTRIDE 132
#define ABUF (128 * ASTRIDE)        // 4608 floats
#define BBUF (32 * BSTRIDE)         // 4224 floats
#define GEMM_SMEM ((2 * ABUF + 2 * BBUF) * 4)   // 70656 bytes

__global__ __launch_bounds__(256, 1) void mma_gemm(
    const float* __restrict__ A, const float* __restrict__ B,
    const float* __restrict__ bias, float* __restrict__ C,
    int M, int N, int K, int do_relu)
{
    extern __shared__ float sm[];
    float* AsB = sm;                // 2 x ABUF
    float* BsB = sm + 2 * ABUF;     // 2 x BBUF

    const int tid  = threadIdx.x;
    const int bm   = blockIdx.y * 128;
    const int bn   = blockIdx.x * 128;
    const int lane = tid & 31;
    const int warp = tid >> 5;
    const int g    = lane >> 2;     // 0..7
    const int t    = lane & 3;      // 0..3
    const int m0   = (warp & 1) * 64;
    const int n0   = (warp >> 1) * 32;

    float acc[4][4][4];
    #pragma unroll
    for (int i = 0; i < 4; i++)
        #pragma unroll
        for (int j = 0; j < 4; j++)
            #pragma unroll
            for (int e = 0; e < 4; e++) acc[i][j][e] = 0.f;

    // staging index precompute
    const int ar = tid >> 1;              // A: row tid>>1
    const int ac = (tid & 1) * 16;        // col 0 or 16
    const int br = tid >> 3;              // B: row 0..31
    const int bc = (tid & 7) * 16;        // col group of 16

    const int NC = K / 32;
    float4 pa[4], pb[4];

    // ---- stage chunk 0 into buf 0 ----
    {
        #pragma unroll
        for (int i = 0; i < 4; i++)
            pa[i] = *(const float4*)(A + (size_t)(bm + ar) * K + ac + i * 4);
        #pragma unroll
        for (int i = 0; i < 4; i++)
            pb[i] = *(const float4*)(B + (size_t)br * N + bn + bc + i * 4);
        float* Ad = AsB;
        float* Bd = BsB;
        #pragma unroll
        for (int i = 0; i < 4; i++) {
            uint4 u;
            u.x = f2tf32(pa[i].x); u.y = f2tf32(pa[i].y);
            u.z = f2tf32(pa[i].z); u.w = f2tf32(pa[i].w);
            *(uint4*)(Ad + ar * ASTRIDE + ac + i * 4) = u;
        }
        #pragma unroll
        for (int i = 0; i < 4; i++) {
            uint4 u;
            u.x = f2tf32(pb[i].x); u.y = f2tf32(pb[i].y);
            u.z = f2tf32(pb[i].z); u.w = f2tf32(pb[i].w);
            *(uint4*)(Bd + br * BSTRIDE + bc + i * 4) = u;
        }
    }
    __syncthreads();

    for (int c = 0; c < NC; c++) {
        const int buf = c & 1;
        if (c + 1 < NC) {
            const int k0 = (c + 1) * 32;
            #pragma unroll
            for (int i = 0; i < 4; i++)
                pa[i] = *(const float4*)(A + (size_t)(bm + ar) * K + k0 + ac + i * 4);
            #pragma unroll
            for (int i = 0; i < 4; i++)
                pb[i] = *(const float4*)(B + (size_t)(k0 + br) * N + bn + bc + i * 4);
        }

        const uint32_t* Au = (const uint32_t*)(AsB + buf * ABUF);
        const uint32_t* Bu = (const uint32_t*)(BsB + buf * BBUF);

        #pragma unroll
        for (int ks = 0; ks < 4; ks++) {
            const int kk = ks * 8;
            uint32_t af[4][4];
            #pragma unroll
            for (int mf = 0; mf < 4; mf++) {
                const int r = m0 + mf * 16 + g;
                af[mf][0] = Au[r * ASTRIDE + kk + t];
                af[mf][1] = Au[(r + 8) * ASTRIDE + kk + t];
                af[mf][2] = Au[r * ASTRIDE + kk + t + 4];
                af[mf][3] = Au[(r + 8) * ASTRIDE + kk + t + 4];
            }
            #pragma unroll
            for (int nf = 0; nf < 4; nf++) {
                const int cn = n0 + nf * 8 + g;
                uint32_t b0 = Bu[(kk + t) * BSTRIDE + cn];
                uint32_t b1 = Bu[(kk + t + 4) * BSTRIDE + cn];
                #pragma unroll
                for (int mf = 0; mf < 4; mf++)
                    mma_tf32(acc[mf][nf], af[mf][0], af[mf][1], af[mf][2], af[mf][3], b0, b1);
            }
        }

        if (c + 1 < NC) {
            const int nb = (c + 1) & 1;
            float* Ad = AsB + nb * ABUF;
            float* Bd = BsB + nb * BBUF;
            #pragma unroll
            for (int i = 0; i < 4; i++) {
                uint4 u;
                u.x = f2tf32(pa[i].x); u.y = f2tf32(pa[i].y);
                u.z = f2tf32(pa[i].z); u.w = f2tf32(pa[i].w);
                *(uint4*)(Ad + ar * ASTRIDE + ac + i * 4) = u;
            }
            #pragma unroll
            for (int i = 0; i < 4; i++) {
                uint4 u;
                u.x = f2tf32(pb[i].x); u.y = f2tf32(pb[i].y);
                u.z = f2tf32(pb[i].z); u.w = f2tf32(pb[i].w);
                *(uint4*)(Bd + br * BSTRIDE + bc + i * 4) = u;
            }
            __syncthreads();
        }
    }

    // ---- epilogue ----
    #pragma unroll
    for (int mf = 0; mf < 4; mf++) {
        const int r0 = bm + m0 + mf * 16 + g;
        #pragma unroll
        for (int nf = 0; nf < 4; nf++) {
            const int col = bn + n0 + nf * 8 + 2 * t;
            const float b0 = bias[col], b1 = bias[col + 1];
            float2 o0, o1;
            o0.x = acc[mf][nf][0] + b0; o0.y = acc[mf][nf][1] + b1;
            o1.x = acc[mf][nf][2] + b0; o1.y = acc[mf][nf][3] + b1;
            if (do_relu) {
                o0.x = fmaxf(o0.x, 0.f); o0.y = fmaxf(o0.y, 0.f);
                o1.x = fmaxf(o1.x, 0.f); o1.y = fmaxf(o1.y, 0.f);
            }
            *(float2*)(C + (size_t)r0 * N + col)       = o0;
            *(float2*)(C + (size_t)(r0 + 8) * N + col) = o1;
        }
    }
}

// ---------------- copy ----------------
__global__ void copy_kernel(const float* __restrict__ src, float* __restrict__ dst, int n)
{
    int i = blockIdx.x * blockDim.x + threadIdx.x;
    if (i < n) dst[i] = src[i];
}

// ---------------- FAVOR feature map ----------------
__global__ __launch_bounds__(256) void favor_kernel(
    const float* __restrict__ X, const float* __restrict__ omega,
    float* __restrict__ Phi)
{
    __shared__ float om[DH * 32];
    __shared__ float xsb[8][DH];

    const int tid = threadIdx.x;
    for (int i = tid; i < DH * 32; i += 256) om[i] = omega[i];

    const int w    = tid >> 5;
    const int lane = tid & 31;
    const int gw   = blockIdx.x * 8 + w;
    const int token = gw >> 4;
    const int head  = gw & 15;

    const float scale = 0.35355339059327373f;   // 64^-0.25
    const size_t base = (size_t)token * D_MODEL + head * DH;

    float x0 = X[base + lane]      * scale;
    float x1 = X[base + 32 + lane] * scale;
    xsb[w][lane]      = x0;
    xsb[w][lane + 32] = x1;

    float hh = x0 * x0 + x1 * x1;
    #pragma unroll
    for (int o = 16; o; o >>= 1) hh += __shfl_xor_sync(0xffffffffu, hh, o);
    hh *= 0.5f;

    __syncthreads();

    float u = 0.f;
    #pragma unroll
    for (int d = 0; d < DH; d++)
        u = fmaf(xsb[w][d], om[d * 32 + lane], u);

    const float c = 0.125f;   // 64^-0.5
    Phi[base + lane]      = expf(u  - hh) * c;
    Phi[base + 32 + lane] = expf(-u - hh) * c;
}

// ---------------- chunked causal linear attention ----------------
// Phase 1: per-chunk sums  S_c = sum_{t in c} k_t v_t^T ,  z_c = sum k_t
__global__ __launch_bounds__(64) void chunk_sums_kernel(
    const float* __restrict__ Kf, const float* __restrict__ V,
    float* __restrict__ gS, float* __restrict__ gZ)
{
    const int ch = blockIdx.x;        // 0..15
    const int bh = blockIdx.y;        // 0..31
    const int d  = threadIdx.x;       // 0..63
    __shared__ float ksbuf[64];

    const int b = bh >> 4, hh = bh & 15;
    const size_t base = (size_t)b * 1024 * D_MODEL + hh * DH + d;
    const int t0 = ch * CLEN;

    float S[64];
    #pragma unroll
    for (int m = 0; m < 64; m++) S[m] = 0.f;
    float zz = 0.f;

    for (int t = 0; t < CLEN; t++) {
        const size_t off = base + (size_t)(t0 + t) * D_MODEL;
        __syncthreads();
        ksbuf[d] = Kf[off];
        const float vd = V[off];
        __syncthreads();
        zz += ksbuf[d];
        #pragma unroll
        for (int m4 = 0; m4 < 16; m4++) {
            float4 k4 = *(const float4*)&ksbuf[m4 * 4];
            S[m4*4+0] = fmaf(k4.x, vd, S[m4*4+0]);
            S[m4*4+1] = fmaf(k4.y, vd, S[m4*4+1]);
            S[m4*4+2] = fmaf(k4.z, vd, S[m4*4+2]);
            S[m4*4+3] = fmaf(k4.w, vd, S[m4*4+3]);
        }
    }

    const size_t idx = (size_t)(bh * NCHUNK + ch);
    float* Sp = gS + idx * 64 * 64;
    #pragma unroll
    for (int m = 0; m < 64; m++) Sp[m * 64 + d] = S[m];
    gZ[idx * 64 + d] = zz;
}

// Phase 2: exclusive prefix over chunks (in-place), per (b,h)
__global__ __launch_bounds__(64) void chunk_prefix_kernel(
    float* __restrict__ gS, float* __restrict__ gZ)
{
    const int bh = blockIdx.x;        // 0..31
    const int d  = threadIdx.x;

    float run[64];
    #pragma unroll
    for (int m = 0; m < 64; m++) run[m] = 0.f;
    float zrun = 0.f;

    for (int ch = 0; ch < NCHUNK; ch++) {
        const size_t idx = (size_t)(bh * NCHUNK + ch);
        float* Sp = gS + idx * 64 * 64;
        float tmp[64];
        #pragma unroll
        for (int m = 0; m < 64; m++) tmp[m] = Sp[m * 64 + d];
        #pragma unroll
        for (int m = 0; m < 64; m++) { Sp[m * 64 + d] = run[m]; run[m] += tmp[m]; }
        float zt = gZ[idx * 64 + d];
        gZ[idx * 64 + d] = zrun;
        zrun += zt;
    }
}

// Phase 3: per-chunk sequential scan starting from exclusive prefix state
__global__ __launch_bounds__(64) void chunk_scan_kernel(
    const float* __restrict__ Qf, const float* __restrict__ Kf,
    const float* __restrict__ V, const float* __restrict__ gS,
    const float* __restrict__ gZ, float* __restrict__ Out)
{
    const int ch = blockIdx.x;
    const int bh = blockIdx.y;
    const int d  = threadIdx.x;
    __shared__ __align__(16) float qs[64], ks[64], zs[64];

    const int b = bh >> 4, hh = bh & 15;
    const size_t base = (size_t)b * 1024 * D_MODEL + hh * DH + d;
    const int t0 = ch * CLEN;
    const size_t idx = (size_t)(bh * NCHUNK + ch);

    float S[64];
    const float* Sp = gS + idx * 64 * 64;
    #pragma unroll
    for (int m = 0; m < 64; m++) S[m] = Sp[m * 64 + d];
    zs[d] = gZ[idx * 64 + d];

    for (int t = 0; t < CLEN; t++) {
        const size_t off = base + (size_t)(t0 + t) * D_MODEL;
        __syncthreads();
        qs[d] = Qf[off]; ks[d] = Kf[off];
        const float vd = V[off];
        __syncthreads();
        zs[d] += ks[d];
        __syncthreads();

        float num = 0.f, den = 0.f;
        #pragma unroll
        for (int m4 = 0; m4 < 16; m4++) {
            float4 k4 = *(const float4*)&ks[m4 * 4];
            float4 q4 = *(const float4*)&qs[m4 * 4];
            float4 z4 = *(const float4*)&zs[m4 * 4];
            S[m4*4+0] = fmaf(k4.x, vd, S[m4*4+0]); num = fmaf(q4.x, S[m4*4+0], num); den = fmaf(q4.x, z4.x, den);
            S[m4*4+1] = fmaf(k4.y, vd, S[m4*4+1]); num = fmaf(q4.y, S[m4*4+1], num); den = fmaf(q4.y, z4.y, den);
            S[m4*4+2] = fmaf(k4.z, vd, S[m4*4+2]); num = fmaf(q4.z, S[m4*4+2], num); den = fmaf(q4.z, z4.z, den);
            S[m4*4+3] = fmaf(k4.w, vd, S[m4*4+3]); num = fmaf(q4.w, S[m4*4+3], num); den = fmaf(q4.w, z4.w, den);
        }
        Out[off] = num / (den + 1e-6f);
    }
}

// ---------------- LayerNorm(out = LN(a + r) * g + b) ----------------
__global__ __launch_bounds__(256) void ln_kernel(
    float* __restrict__ out, const float* __restrict__ a,
    const float* __restrict__ r, const float* __restrict__ gam,
    const float* __restrict__ bet)
{
    const int row = blockIdx.x;
    const int tid = threadIdx.x;
    const float* pa = a + (size_t)row * D_MODEL;
    const float* pr = r + (size_t)row * D_MODEL;

    float v[4];
    float s = 0.f, ss = 0.f;
    #pragma unroll
    for (int i = 0; i < 4; i++) {
        int idx = tid + i * 256;
        float t = pa[idx] + pr[idx];
        v[i] = t; s += t; ss = fmaf(t, t, ss);
    }

    __shared__ float red[18];
    #pragma unroll
    for (int o = 16; o; o >>= 1) {
        s  += __shfl_xor_sync(0xffffffffu, s,  o);
        ss += __shfl_xor_sync(0xffffffffu, ss, o);
    }
    const int w = tid >> 5, lane = tid & 31;
    __shared__ float rw[16];
    if (lane == 0) { rw[w] = s; rw[w + 8] = ss; }
    __syncthreads();
    if (tid == 0) {
        float S0 = 0.f, S1 = 0.f;
        #pragma unroll
        for (int i = 0; i < 8; i++) { S0 += rw[i]; S1 += rw[i + 8]; }
        red[16] = S0; red[17] = S1;
    }
    __syncthreads();

    const float mean = red[16] * (1.f / 1024.f);
    const float var  = red[17] * (1.f / 1024.f) - mean * mean;
    const float inv  = rsqrtf(var + 1e-5f);

    float* po = out + (size_t)row * D_MODEL;
    #pragma unroll
    for (int i = 0; i < 4; i++) {
        int idx = tid + i * 256;
        po[idx] = (v[i] - mean) * inv * gam[idx] + bet[idx];
    }
}

// ---------------- launch ----------------
extern "C" void kernel_launch(void* const* d_in, const int* in_sizes, int n_in,
                              void* d_out, int out_size)
{
    const float* x    = (const float*)d_in[0];
    const float* Wq   = (const float*)d_in[1];
    const float* bq   = (const float*)d_in[2];
    const float* Wk   = (const float*)d_in[3];
    const float* bk   = (const float*)d_in[4];
    const float* Wv   = (const float*)d_in[5];
    const float* bv   = (const float*)d_in[6];
    const float* Wo   = (const float*)d_in[7];
    const float* bo   = (const float*)d_in[8];
    const float* omg  = (const float*)d_in[9];
    const float* ln1g = (const float*)d_in[10];
    const float* ln1b = (const float*)d_in[11];
    const float* ln2g = (const float*)d_in[12];
    const float* ln2b = (const float*)d_in[13];
    const float* W1   = (const float*)d_in[14];
    const float* bf1  = (const float*)d_in[15];
    const float* W2   = (const float*)d_in[16];
    const float* bf2  = (const float*)d_in[17];
    float* out = (float*)d_out;

    float *cur, *q, *k, *v, *qf, *kf, *h, *ffn, *gS, *gZ;
    cudaGetSymbolAddress((void**)&cur, g_cur);
    cudaGetSymbolAddress((void**)&q,   g_q);
    cudaGetSymbolAddress((void**)&k,   g_k);
    cudaGetSymbolAddress((void**)&v,   g_v);
    cudaGetSymbolAddress((void**)&qf,  g_qf);
    cudaGetSymbolAddress((void**)&kf,  g_kf);
    cudaGetSymbolAddress((void**)&h,   g_h);
    cudaGetSymbolAddress((void**)&ffn, g_ffn);
    cudaGetSymbolAddress((void**)&gS,  g_S);
    cudaGetSymbolAddress((void**)&gZ,  g_Z);

    cudaFuncSetAttribute(mma_gemm, cudaFuncAttributeMaxDynamicSharedMemorySize, GEMM_SMEM);

    const int nElem = NTOK * D_MODEL;
    copy_kernel<<<(nElem + 255) / 256, 256>>>(x, cur, nElem);

    const dim3 gD(D_MODEL / 128, NTOK / 128);          // (8,16)
    const dim3 gF(DFF_DIM / 128, NTOK / 128);          // (32,16)
    const dim3 gCh(NCHUNK, 32);                        // (chunk, bh)

    for (int l = 0; l < NLAYER; l++) {
        const size_t wDD  = (size_t)l * D_MODEL * D_MODEL;
        const size_t wDF  = (size_t)l * D_MODEL * DFF_DIM;
        const size_t bD   = (size_t)l * D_MODEL;
        const size_t bF   = (size_t)l * DFF_DIM;
        const size_t oOff = (size_t)l * DH * 32;

        mma_gemm<<<gD, 256, GEMM_SMEM>>>(cur, Wq + wDD, bq + bD, q, NTOK, D_MODEL, D_MODEL, 0);
        mma_gemm<<<gD, 256, GEMM_SMEM>>>(cur, Wk + wDD, bk + bD, k, NTOK, D_MODEL, D_MODEL, 0);
        mma_gemm<<<gD, 256, GEMM_SMEM>>>(cur, Wv + wDD, bv + bD, v, NTOK, D_MODEL, D_MODEL, 0);

        favor_kernel<<<NTOK * NHEAD / 8, 256>>>(q, omg + oOff, qf);
        favor_kernel<<<NTOK * NHEAD / 8, 256>>>(k, omg + oOff, kf);

        chunk_sums_kernel<<<gCh, 64>>>(kf, v, gS, gZ);
        chunk_prefix_kernel<<<32, 64>>>(gS, gZ);
        chunk_scan_kernel<<<gCh, 64>>>(qf, kf, v, gS, gZ, q);   // attn -> q

        mma_gemm<<<gD, 256, GEMM_SMEM>>>(q, Wo + wDD, bo + bD, k, NTOK, D_MODEL, D_MODEL, 0);
        ln_kernel<<<NTOK, 256>>>(h, cur, k, ln1g + bD, ln1b + bD);

        mma_gemm<<<gF, 256, GEMM_SMEM>>>(h, W1 + wDF, bf1 + bF, ffn, NTOK, DFF_DIM, D_MODEL, 1);
        mma_gemm<<<gD, 256, GEMM_SMEM>>>(ffn, W2 + wDF, bf2 + bD, v, NTOK, D_MODEL, DFF_DIM, 0);

        float* dst = (l == NLAYER - 1) ? out : cur;
        ln_kernel<<<NTOK, 256>>>(dst, h, v, ln2g + bD, ln2b + bD);
    }
}

// round 5
// speedup vs baseline: 2.7158x; 1.1409x over previous
#include <cuda_runtime.h>
#include <cstdint>
#include <math.h>

// ---------------- problem constants ----------------
#define D_MODEL 1024
#define DFF_DIM 4096
#define NTOK    2048          // B*S = 2*1024
#define NHEAD   16
#define DH      64
#define NLAYER  3
#define NCHUNK  16            // chunks per sequence
#define CLEN    64            // tokens per chunk

// ---------------- scratch (no allocs allowed) ----------------
__device__ float g_cur[NTOK * D_MODEL];
__device__ float g_q  [NTOK * D_MODEL];
__device__ float g_k  [NTOK * D_MODEL];
__device__ float g_v  [NTOK * D_MODEL];
__device__ float g_qf [NTOK * D_MODEL];
__device__ float g_kf [NTOK * D_MODEL];
__device__ float g_h  [NTOK * D_MODEL];
__device__ float g_ffn[NTOK * DFF_DIM];
__device__ float g_S  [32 * NCHUNK * DH * DH];
__device__ float g_Z  [32 * NCHUNK * DH];

// ================= helpers =================
__device__ __forceinline__ uint32_t f2tf32(float f) {
    uint32_t u;
    asm("cvt.rna.tf32.f32 %0, %1;" : "=r"(u) : "f"(f));
    return u;
}
__device__ __forceinline__ void mma_tf32(float c[4], uint32_t a0, uint32_t a1,
                                         uint32_t a2, uint32_t a3,
                                         uint32_t b0, uint32_t b1) {
    asm volatile(
        "mma.sync.aligned.m16n8k8.row.col.f32.tf32.tf32.f32 "
        "{%0,%1,%2,%3}, {%4,%5,%6,%7}, {%8,%9}, {%0,%1,%2,%3};"
        : "+f"(c[0]), "+f"(c[1]), "+f"(c[2]), "+f"(c[3])
        : "r"(a0), "r"(a1), "r"(a2), "r"(a3), "r"(b0), "r"(b1));
}

// ================= TF32 tensor-core GEMM =================
// C[M,N] = A[M,K] @ B[K,N] + bias (optional relu).
// 128x128 CTA tile, BK=64, 256 threads (8 warps, warp tile 64x32).
// Double-buffered; next chunk staged in two 32-wide halves interleaved
// between the two MMA half-phases of the current chunk.
// ASTRIDE=68 (=4 mod 32): A-frag LDS conflict-free.
// BSTRIDE=136 (=8 mod 32): B-frag LDS conflict-free.
#define BK      64
#define ASTRIDE 68
#define BSTRIDE 136
#define ABUF (128 * ASTRIDE)        // words
#define BBUF (64 * BSTRIDE)         // words
#define GEMM_SMEM ((2 * ABUF + 2 * BBUF) * 4)   // 139264 bytes

// stage one 32-wide K half: LDG into regs
__device__ __forceinline__ void ldg_half(
    const float* __restrict__ A, const float* __restrict__ B,
    int K, int N, int bm, int bn, int k0, int koff,
    int ar, int ac, int br, int bc, float4 pa[4], float4 pb[4])
{
    const float* Ap = A + (size_t)(bm + ar) * K + k0 + koff + ac;
    #pragma unroll
    for (int i = 0; i < 4; i++) pa[i] = *(const float4*)(Ap + i * 4);
    const float* Bp = B + (size_t)(k0 + koff + br) * N + bn + bc;
    #pragma unroll
    for (int i = 0; i < 4; i++) pb[i] = *(const float4*)(Bp + i * 4);
}
// cvt + STS one half into buffer at k-offset koff
__device__ __forceinline__ void sts_half(
    float* Ad, float* Bd, int koff,
    int ar, int ac, int br, int bc, const float4 pa[4], const float4 pb[4])
{
    #pragma unroll
    for (int i = 0; i < 4; i++) {
        uint4 u;
        u.x = f2tf32(pa[i].x); u.y = f2tf32(pa[i].y);
        u.z = f2tf32(pa[i].z); u.w = f2tf32(pa[i].w);
        *(uint4*)(Ad + ar * ASTRIDE + koff + ac + i * 4) = u;
    }
    #pragma unroll
    for (int i = 0; i < 4; i++) {
        uint4 u;
        u.x = f2tf32(pb[i].x); u.y = f2tf32(pb[i].y);
        u.z = f2tf32(pb[i].z); u.w = f2tf32(pb[i].w);
        *(uint4*)(Bd + (koff + br) * BSTRIDE + bc + i * 4) = u;
    }
}

__global__ __launch_bounds__(256, 1) void mma_gemm(
    const float* __restrict__ A,
    const float* __restrict__ B0, const float* __restrict__ B1, const float* __restrict__ B2,
    const float* __restrict__ bias0, const float* __restrict__ bias1, const float* __restrict__ bias2,
    float* __restrict__ C0, float* __restrict__ C1, float* __restrict__ C2,
    int M, int N, int K, int do_relu)
{
    extern __shared__ float sm[];
    float* AsB = sm;                // 2 x ABUF
    float* BsB = sm + 2 * ABUF;     // 2 x BBUF

    const int z = blockIdx.z;
    const float* B    = (z == 0) ? B0 : (z == 1) ? B1 : B2;
    const float* bias = (z == 0) ? bias0 : (z == 1) ? bias1 : bias2;
    float* C          = (z == 0) ? C0 : (z == 1) ? C1 : C2;

    const int tid  = threadIdx.x;
    const int bm   = blockIdx.y * 128;
    const int bn   = blockIdx.x * 128;
    const int lane = tid & 31;
    const int warp = tid >> 5;
    const int g    = lane >> 2;     // 0..7
    const int t    = lane & 3;      // 0..3
    const int m0   = (warp & 1) * 64;
    const int n0   = (warp >> 1) * 32;

    float acc[4][4][4];
    #pragma unroll
    for (int i = 0; i < 4; i++)
        #pragma unroll
        for (int j = 0; j < 4; j++)
            #pragma unroll
            for (int e = 0; e < 4; e++) acc[i][j][e] = 0.f;

    // staging index precompute (per 32-wide half)
    const int ar = tid >> 1;              // 0..127
    const int ac = (tid & 1) * 16;        // 0 or 16
    const int br = tid >> 3;              // 0..31
    const int bc = (tid & 7) * 16;        // 0..112

    const int NC = K / BK;
    float4 pa[4], pb[4];

    // ---- prologue: stage chunk 0 (both halves) into buf 0 ----
    ldg_half(A, B, K, N, bm, bn, 0, 0,  ar, ac, br, bc, pa, pb);
    sts_half(AsB, BsB, 0,  ar, ac, br, bc, pa, pb);
    ldg_half(A, B, K, N, bm, bn, 0, 32, ar, ac, br, bc, pa, pb);
    sts_half(AsB, BsB, 32, ar, ac, br, bc, pa, pb);
    __syncthreads();

    for (int c = 0; c < NC; c++) {
        const int buf = c & 1;
        const int nb  = buf ^ 1;
        const uint32_t* Au = (const uint32_t*)(AsB + buf * ABUF);
        const uint32_t* Bu = (const uint32_t*)(BsB + buf * BBUF);
        float* Ad = AsB + nb * ABUF;
        float* Bd = BsB + nb * BBUF;
        const bool more = (c + 1 < NC);

        if (more) ldg_half(A, B, K, N, bm, bn, (c + 1) * BK, 0, ar, ac, br, bc, pa, pb);

        // ---- MMA half 1 (ks 0..3) ----
        #pragma unroll
        for (int ks = 0; ks < 4; ks++) {
            const int kk = ks * 8;
            uint32_t af[4][4];
            #pragma unroll
            for (int mf = 0; mf < 4; mf++) {
                const int r = m0 + mf * 16 + g;
                af[mf][0] = Au[r * ASTRIDE + kk + t];
                af[mf][1] = Au[(r + 8) * ASTRIDE + kk + t];
                af[mf][2] = Au[r * ASTRIDE + kk + t + 4];
                af[mf][3] = Au[(r + 8) * ASTRIDE + kk + t + 4];
            }
            #pragma unroll
            for (int nf = 0; nf < 4; nf++) {
                const int cn = n0 + nf * 8 + g;
                uint32_t b0 = Bu[(kk + t) * BSTRIDE + cn];
                uint32_t b1 = Bu[(kk + t + 4) * BSTRIDE + cn];
                #pragma unroll
                for (int mf = 0; mf < 4; mf++)
                    mma_tf32(acc[mf][nf], af[mf][0], af[mf][1], af[mf][2], af[mf][3], b0, b1);
            }
        }

        if (more) {
            sts_half(Ad, Bd, 0, ar, ac, br, bc, pa, pb);
            ldg_half(A, B, K, N, bm, bn, (c + 1) * BK, 32, ar, ac, br, bc, pa, pb);
        }

        // ---- MMA half 2 (ks 4..7) ----
        #pragma unroll
        for (int ks = 4; ks < 8; ks++) {
            const int kk = ks * 8;
            uint32_t af[4][4];
            #pragma unroll
            for (int mf = 0; mf < 4; mf++) {
                const int r = m0 + mf * 16 + g;
                af[mf][0] = Au[r * ASTRIDE + kk + t];
                af[mf][1] = Au[(r + 8) * ASTRIDE + kk + t];
                af[mf][2] = Au[r * ASTRIDE + kk + t + 4];
                af[mf][3] = Au[(r + 8) * ASTRIDE + kk + t + 4];
            }
            #pragma unroll
            for (int nf = 0; nf < 4; nf++) {
                const int cn = n0 + nf * 8 + g;
                uint32_t b0 = Bu[(kk + t) * BSTRIDE + cn];
                uint32_t b1 = Bu[(kk + t + 4) * BSTRIDE + cn];
                #pragma unroll
                for (int mf = 0; mf < 4; mf++)
                    mma_tf32(acc[mf][nf], af[mf][0], af[mf][1], af[mf][2], af[mf][3], b0, b1);
            }
        }

        if (more) {
            sts_half(Ad, Bd, 32, ar, ac, br, bc, pa, pb);
            __syncthreads();
        }
    }

    // ---- epilogue ----
    #pragma unroll
    for (int mf = 0; mf < 4; mf++) {
        const int r0 = bm + m0 + mf * 16 + g;
        #pragma unroll
        for (int nf = 0; nf < 4; nf++) {
            const int col = bn + n0 + nf * 8 + 2 * t;
            const float b0 = bias[col], b1 = bias[col + 1];
            float2 o0, o1;
            o0.x = acc[mf][nf][0] + b0; o0.y = acc[mf][nf][1] + b1;
            o1.x = acc[mf][nf][2] + b0; o1.y = acc[mf][nf][3] + b1;
            if (do_relu) {
                o0.x = fmaxf(o0.x, 0.f); o0.y = fmaxf(o0.y, 0.f);
                o1.x = fmaxf(o1.x, 0.f); o1.y = fmaxf(o1.y, 0.f);
            }
            *(float2*)(C + (size_t)r0 * N + col)       = o0;
            *(float2*)(C + (size_t)(r0 + 8) * N + col) = o1;
        }
    }
}

// ---------------- copy ----------------
__global__ void copy_kernel(const float* __restrict__ src, float* __restrict__ dst, int n)
{
    int i = blockIdx.x * blockDim.x + threadIdx.x;
    if (i < n) dst[i] = src[i];
}

// ---------------- FAVOR feature map (fused q/k via blockIdx.y) ----------------
__global__ __launch_bounds__(256) void favor_kernel(
    const float* __restrict__ X0, const float* __restrict__ X1,
    const float* __restrict__ omega,
    float* __restrict__ P0, float* __restrict__ P1)
{
    __shared__ float om[DH * 32];
    __shared__ float xsb[8][DH];

    const float* X   = blockIdx.y ? X1 : X0;
    float* Phi       = blockIdx.y ? P1 : P0;

    const int tid = threadIdx.x;
    for (int i = tid; i < DH * 32; i += 256) om[i] = omega[i];

    const int w    = tid >> 5;
    const int lane = tid & 31;
    const int gw   = blockIdx.x * 8 + w;
    const int token = gw >> 4;
    const int head  = gw & 15;

    const float scale = 0.35355339059327373f;   // 64^-0.25
    const size_t base = (size_t)token * D_MODEL + head * DH;

    float x0 = X[base + lane]      * scale;
    float x1 = X[base + 32 + lane] * scale;
    xsb[w][lane]      = x0;
    xsb[w][lane + 32] = x1;

    float hh = x0 * x0 + x1 * x1;
    #pragma unroll
    for (int o = 16; o; o >>= 1) hh += __shfl_xor_sync(0xffffffffu, hh, o);
    hh *= 0.5f;

    __syncthreads();

    float u = 0.f;
    #pragma unroll
    for (int d = 0; d < DH; d++)
        u = fmaf(xsb[w][d], om[d * 32 + lane], u);

    const float c = 0.125f;   // 64^-0.5
    Phi[base + lane]      = expf(u  - hh) * c;
    Phi[base + 32 + lane] = expf(-u - hh) * c;
}

// ---------------- chunked causal linear attention ----------------
__global__ __launch_bounds__(64) void chunk_sums_kernel(
    const float* __restrict__ Kf, const float* __restrict__ V,
    float* __restrict__ gS, float* __restrict__ gZ)
{
    const int ch = blockIdx.x;
    const int bh = blockIdx.y;
    const int d  = threadIdx.x;
    __shared__ float ksbuf[64];

    const int b = bh >> 4, hh = bh & 15;
    const size_t base = (size_t)b * 1024 * D_MODEL + hh * DH + d;
    const int t0 = ch * CLEN;

    float S[64];
    #pragma unroll
    for (int m = 0; m < 64; m++) S[m] = 0.f;
    float zz = 0.f;

    for (int t = 0; t < CLEN; t++) {
        const size_t off = base + (size_t)(t0 + t) * D_MODEL;
        __syncthreads();
        ksbuf[d] = Kf[off];
        const float vd = V[off];
        __syncthreads();
        zz += ksbuf[d];
        #pragma unroll
        for (int m4 = 0; m4 < 16; m4++) {
            float4 k4 = *(const float4*)&ksbuf[m4 * 4];
            S[m4*4+0] = fmaf(k4.x, vd, S[m4*4+0]);
            S[m4*4+1] = fmaf(k4.y, vd, S[m4*4+1]);
            S[m4*4+2] = fmaf(k4.z, vd, S[m4*4+2]);
            S[m4*4+3] = fmaf(k4.w, vd, S[m4*4+3]);
        }
    }

    const size_t idx = (size_t)(bh * NCHUNK + ch);
    float* Sp = gS + idx * 64 * 64;
    #pragma unroll
    for (int m = 0; m < 64; m++) Sp[m * 64 + d] = S[m];
    gZ[idx * 64 + d] = zz;
}

__global__ __launch_bounds__(64) void chunk_prefix_kernel(
    float* __restrict__ gS, float* __restrict__ gZ)
{
    const int bh = blockIdx.x;
    const int d  = threadIdx.x;

    float run[64];
    #pragma unroll
    for (int m = 0; m < 64; m++) run[m] = 0.f;
    float zrun = 0.f;

    for (int ch = 0; ch < NCHUNK; ch++) {
        const size_t idx = (size_t)(bh * NCHUNK + ch);
        float* Sp = gS + idx * 64 * 64;
        float tmp[64];
        #pragma unroll
        for (int m = 0; m < 64; m++) tmp[m] = Sp[m * 64 + d];
        #pragma unroll
        for (int m = 0; m < 64; m++) { Sp[m * 64 + d] = run[m]; run[m] += tmp[m]; }
        float zt = gZ[idx * 64 + d];
        gZ[idx * 64 + d] = zrun;
        zrun += zt;
    }
}

__global__ __launch_bounds__(64) void chunk_scan_kernel(
    const float* __restrict__ Qf, const float* __restrict__ Kf,
    const float* __restrict__ V, const float* __restrict__ gS,
    const float* __restrict__ gZ, float* __restrict__ Out)
{
    const int ch = blockIdx.x;
    const int bh = blockIdx.y;
    const int d  = threadIdx.x;
    __shared__ __align__(16) float qs[64], ks[64], zs[64];

    const int b = bh >> 4, hh = bh & 15;
    const size_t base = (size_t)b * 1024 * D_MODEL + hh * DH + d;
    const int t0 = ch * CLEN;
    const size_t idx = (size_t)(bh * NCHUNK + ch);

    float S[64];
    const float* Sp = gS + idx * 64 * 64;
    #pragma unroll
    for (int m = 0; m < 64; m++) S[m] = Sp[m * 64 + d];
    zs[d] = gZ[idx * 64 + d];

    for (int t = 0; t < CLEN; t++) {
        const size_t off = base + (size_t)(t0 + t) * D_MODEL;
        __syncthreads();
        qs[d] = Qf[off]; ks[d] = Kf[off];
        const float vd = V[off];
        __syncthreads();
        zs[d] += ks[d];
        __syncthreads();

        float num = 0.f, den = 0.f;
        #pragma unroll
        for (int m4 = 0; m4 < 16; m4++) {
            float4 k4 = *(const float4*)&ks[m4 * 4];
            float4 q4 = *(const float4*)&qs[m4 * 4];
            float4 z4 = *(const float4*)&zs[m4 * 4];
            S[m4*4+0] = fmaf(k4.x, vd, S[m4*4+0]); num = fmaf(q4.x, S[m4*4+0], num); den = fmaf(q4.x, z4.x, den);
            S[m4*4+1] = fmaf(k4.y, vd, S[m4*4+1]); num = fmaf(q4.y, S[m4*4+1], num); den = fmaf(q4.y, z4.y, den);
            S[m4*4+2] = fmaf(k4.z, vd, S[m4*4+2]); num = fmaf(q4.z, S[m4*4+2], num); den = fmaf(q4.z, z4.z, den);
            S[m4*4+3] = fmaf(k4.w, vd, S[m4*4+3]); num = fmaf(q4.w, S[m4*4+3], num); den = fmaf(q4.w, z4.w, den);
        }
        Out[off] = num / (den + 1e-6f);
    }
}

// ---------------- LayerNorm(out = LN(a + r) * g + b) ----------------
__global__ __launch_bounds__(256) void ln_kernel(
    float* __restrict__ out, const float* __restrict__ a,
    const float* __restrict__ r, const float* __restrict__ gam,
    const float* __restrict__ bet)
{
    const int row = blockIdx.x;
    const int tid = threadIdx.x;
    const float* pa = a + (size_t)row * D_MODEL;
    const float* pr = r + (size_t)row * D_MODEL;

    float v[4];
    float s = 0.f, ss = 0.f;
    #pragma unroll
    for (int i = 0; i < 4; i++) {
        int idx = tid + i * 256;
        float t = pa[idx] + pr[idx];
        v[i] = t; s += t; ss = fmaf(t, t, ss);
    }

    __shared__ float red[18];
    #pragma unroll
    for (int o = 16; o; o >>= 1) {
        s  += __shfl_xor_sync(0xffffffffu, s,  o);
        ss += __shfl_xor_sync(0xffffffffu, ss, o);
    }
    const int w = tid >> 5, lane = tid & 31;
    __shared__ float rw[16];
    if (lane == 0) { rw[w] = s; rw[w + 8] = ss; }
    __syncthreads();
    if (tid == 0) {
        float S0 = 0.f, S1 = 0.f;
        #pragma unroll
        for (int i = 0; i < 8; i++) { S0 += rw[i]; S1 += rw[i + 8]; }
        red[16] = S0; red[17] = S1;
    }
    __syncthreads();

    const float mean = red[16] * (1.f / 1024.f);
    const float var  = red[17] * (1.f / 1024.f) - mean * mean;
    const float inv  = rsqrtf(var + 1e-5f);

    float* po = out + (size_t)row * D_MODEL;
    #pragma unroll
    for (int i = 0; i < 4; i++) {
        int idx = tid + i * 256;
        po[idx] = (v[i] - mean) * inv * gam[idx] + bet[idx];
    }
}

// ---------------- launch ----------------
extern "C" void kernel_launch(void* const* d_in, const int* in_sizes, int n_in,
                              void* d_out, int out_size)
{
    const float* x    = (const float*)d_in[0];
    const float* Wq   = (const float*)d_in[1];
    const float* bq   = (const float*)d_in[2];
    const float* Wk   = (const float*)d_in[3];
    const float* bk   = (const float*)d_in[4];
    const float* Wv   = (const float*)d_in[5];
    const float* bv   = (const float*)d_in[6];
    const float* Wo   = (const float*)d_in[7];
    const float* bo   = (const float*)d_in[8];
    const float* omg  = (const float*)d_in[9];
    const float* ln1g = (const float*)d_in[10];
    const float* ln1b = (const float*)d_in[11];
    const float* ln2g = (const float*)d_in[12];
    const float* ln2b = (const float*)d_in[13];
    const float* W1   = (const float*)d_in[14];
    const float* bf1  = (const float*)d_in[15];
    const float* W2   = (const float*)d_in[16];
    const float* bf2  = (const float*)d_in[17];
    float* out = (float*)d_out;

    float *cur, *q, *k, *v, *qf, *kf, *h, *ffn, *gS, *gZ;
    cudaGetSymbolAddress((void**)&cur, g_cur);
    cudaGetSymbolAddress((void**)&q,   g_q);
    cudaGetSymbolAddress((void**)&k,   g_k);
    cudaGetSymbolAddress((void**)&v,   g_v);
    cudaGetSymbolAddress((void**)&qf,  g_qf);
    cudaGetSymbolAddress((void**)&kf,  g_kf);
    cudaGetSymbolAddress((void**)&h,   g_h);
    cudaGetSymbolAddress((void**)&ffn, g_ffn);
    cudaGetSymbolAddress((void**)&gS,  g_S);
    cudaGetSymbolAddress((void**)&gZ,  g_Z);

    cudaFuncSetAttribute(mma_gemm, cudaFuncAttributeMaxDynamicSharedMemorySize, GEMM_SMEM);

    const int nElem = NTOK * D_MODEL;
    copy_kernel<<<(nElem + 255) / 256, 256>>>(x, cur, nElem);

    const dim3 gQKV(D_MODEL / 128, NTOK / 128, 3);     // (8,16,3)
    const dim3 gD(D_MODEL / 128, NTOK / 128, 1);       // (8,16)
    const dim3 gF(DFF_DIM / 128, NTOK / 128, 1);       // (32,16)
    const dim3 gCh(NCHUNK, 32);
    const dim3 gFav(NTOK * NHEAD / 8, 2);

    for (int l = 0; l < NLAYER; l++) {
        const size_t wDD  = (size_t)l * D_MODEL * D_MODEL;
        const size_t wDF  = (size_t)l * D_MODEL * DFF_DIM;
        const size_t bD   = (size_t)l * D_MODEL;
        const size_t bF   = (size_t)l * DFF_DIM;
        const size_t oOff = (size_t)l * DH * 32;

        mma_gemm<<<gQKV, 256, GEMM_SMEM>>>(cur,
            Wq + wDD, Wk + wDD, Wv + wDD,
            bq + bD, bk + bD, bv + bD,
            q, k, v, NTOK, D_MODEL, D_MODEL, 0);

        favor_kernel<<<gFav, 256>>>(q, k, omg + oOff, qf, kf);

        chunk_sums_kernel<<<gCh, 64>>>(kf, v, gS, gZ);
        chunk_prefix_kernel<<<32, 64>>>(gS, gZ);
        chunk_scan_kernel<<<gCh, 64>>>(qf, kf, v, gS, gZ, q);   // attn -> q

        mma_gemm<<<gD, 256, GEMM_SMEM>>>(q,
            Wo + wDD, Wo + wDD, Wo + wDD,
            bo + bD, bo + bD, bo + bD,
            k, k, k, NTOK, D_MODEL, D_MODEL, 0);
        ln_kernel<<<NTOK, 256>>>(h, cur, k, ln1g + bD, ln1b + bD);

        mma_gemm<<<gF, 256, GEMM_SMEM>>>(h,
            W1 + wDF, W1 + wDF, W1 + wDF,
            bf1 + bF, bf1 + bF, bf1 + bF,
            ffn, ffn, ffn, NTOK, DFF_DIM, D_MODEL, 1);
        mma_gemm<<<gD, 256, GEMM_SMEM>>>(ffn,
            W2 + wDF, W2 + wDF, W2 + wDF,
            bf2 + bD, bf2 + bD, bf2 + bD,
            v, v, v, NTOK, D_MODEL, DFF_DIM, 0);

        float* dst = (l == NLAYER - 1) ? out : cur;
        ln_kernel<<<NTOK, 256>>>(dst, h, v, ln2g + bD, ln2b + bD);
    }
}